// round 5
// baseline (speedup 1.0000x reference)
#include <cuda_runtime.h>
#include <math.h>
#include <stdint.h>
#include <stddef.h>

#define D_DIM   512
#define KD      128
#define VD      128
#define VOCAB   10001
#define BATCH   64
#define TDEC    192
#define TENC    512
#define NTHR    256
#define LPLD    10016          // padded row stride for logits partials

// ---------------------------------------------------------------------------
// Persistent state / scratch (device globals; no allocation allowed)
// ---------------------------------------------------------------------------
__device__ float g_h1[BATCH * D_DIM], g_c1[BATCH * D_DIM];
__device__ float g_h2[BATCH * D_DIM], g_c2[BATCH * D_DIM];
__device__ float g_h3[BATCH * D_DIM], g_c3[BATCH * D_DIM];
__device__ float g_ctx[BATCH * VD];
__device__ float g_hid[BATCH * D_DIM];
__device__ float g_Gp[8 * BATCH * 2048];        // LSTM gate partials (ksplit=8)
__device__ float g_Hp[8 * BATCH * D_DIM];       // p1 partials (ksplit=8)
__device__ float g_Lp[8 * BATCH * LPLD];        // logits partials (ksplit=8)
__device__ float g_attn_scratch[BATCH * TENC];
__device__ float g_gen_scratch [TDEC * BATCH];
__device__ unsigned g_flags[1024];              // per-block arrival epochs (monotonic)
__device__ unsigned g_relgen;                   // released generation (monotonic)

struct KP {
    const int*   inputs;
    const float* keys;   const float* values; const int* ulen;
    const float* emb;
    const float* w_ih0; const float* w_hh0; const float* b_ih0; const float* b_hh0;
    const float* w_ih1; const float* w_hh1; const float* b_ih1; const float* b_hh1;
    const float* w_ih2; const float* w_hh2; const float* b_ih2; const float* b_hh2;
    const float* q_w;  const float* q_b;
    const float* p1_w; const float* p1_b; const float* p2_b;
    float* out_logits; float* out_attn; float* out_gen;
};

union Smem {
    struct { float As[16][64]; float Bs[16][64]; } g;                        // 8 KB
    struct { float h3s[D_DIM]; float q[KD]; float arr[TENC];
             float red[NTHR]; float ps[2][VD]; } a;
    struct { float sv[NTHR]; int si[NTHR]; } s;
};

// ---------------------------------------------------------------------------
// Grid barrier: per-block flag store + block-0 checker. No atomic storm.
// Epochs monotonic across graph replays (base read at kernel entry).
// ---------------------------------------------------------------------------
__device__ __forceinline__ void grid_sync(unsigned& e)
{
    e++;
    __syncthreads();
    if (blockIdx.x == 0) {
        const int g = gridDim.x;
        bool ok;
        do {
            ok = true;
            for (int i = threadIdx.x; i < g; i += NTHR)
                if (i != 0 && ((volatile unsigned*)g_flags)[i] < e) ok = false;
            if (!__syncthreads_and(ok)) { __nanosleep(60); continue; }
            break;
        } while (true);
        __threadfence();
        if (threadIdx.x == 0) ((volatile unsigned*)&g_relgen)[0] = e;
    } else {
        if (threadIdx.x == 0) {
            __threadfence();
            ((volatile unsigned*)g_flags)[blockIdx.x] = e;
            while (((volatile unsigned*)&g_relgen)[0] < e) __nanosleep(60);
        }
        __syncthreads();
        __threadfence_block();
    }
    __syncthreads();
}

// ---------------------------------------------------------------------------
// Virtual-operand loaders
// ---------------------------------------------------------------------------
__device__ __forceinline__ float4 ld4(const float* p) { return *reinterpret_cast<const float4*>(p); }

template<int MODE>
__device__ __forceinline__ float4 loadA(const KP& p, int tok, int m, int k)
{
    if (MODE == 0) {
        if (k < 512)      return ld4(p.emb + (size_t)tok * D_DIM + k);
        else if (k < 640) return ld4(g_ctx + m * VD + (k - 512));
        else              return ld4(g_h1 + m * D_DIM + (k - 640));
    } else if (MODE == 1) {
        return (k < 512) ? ld4(g_h1 + m * D_DIM + k) : ld4(g_h2 + m * D_DIM + (k - 512));
    } else if (MODE == 2) {
        return (k < 512) ? ld4(g_h2 + m * D_DIM + k) : ld4(g_h3 + m * D_DIM + (k - 512));
    } else if (MODE == 3) {
        return (k < 512) ? ld4(g_h3 + m * D_DIM + k) : ld4(g_ctx + m * VD + (k - 512));
    } else {
        return ld4(g_hid + m * D_DIM + k);
    }
}

template<int MODE>
__device__ __forceinline__ float4 loadB(const KP& p, int n, int k)
{
    if (MODE == 0) return (k < 640) ? ld4(p.w_ih0 + (size_t)n * 640 + k)
                                    : ld4(p.w_hh0 + (size_t)n * 512 + (k - 640));
    if (MODE == 1) return (k < 512) ? ld4(p.w_ih1 + (size_t)n * 512 + k)
                                    : ld4(p.w_hh1 + (size_t)n * 512 + (k - 512));
    if (MODE == 2) return (k < 512) ? ld4(p.w_ih2 + (size_t)n * 512 + k)
                                    : ld4(p.w_hh2 + (size_t)n * 512 + (k - 512));
    if (MODE == 3) return ld4(p.p1_w + (size_t)n * 640 + k);
    if (n < VOCAB) return ld4(p.emb + (size_t)n * D_DIM + k);
    return make_float4(0.f, 0.f, 0.f, 0.f);
}

// ---------------------------------------------------------------------------
// GEMM: C[m][n] = sum_k A[m][k]*B[n][k], M=64. Tile 64x64, thread-tile 4x4,
// register-prefetch double buffering. Split-K partial outputs.
// ---------------------------------------------------------------------------
template<int MODE, int NN, int KK, int KSPLIT>
__device__ void gemm_phase(const KP& p, Smem& sm, int step, float* out)
{
    constexpr int NT = (NN + 63) / 64;
    constexpr int KC = KK / KSPLIT;
    constexpr int NCH = KC / 16;
    constexpr int NTILES = NT * KSPLIT;
    const int tid = threadIdx.x;
    const int ty = tid >> 4, tx = tid & 15;
    const int lr = tid & 63, lk = (tid >> 6) * 4;

    // rotate tiles so sampler blocks (0..63) get the last tiles
    const int start = (blockIdx.x >= 64) ? (blockIdx.x - 64)
                                         : ((int)gridDim.x - 64 + blockIdx.x);
    int tok = 0;
    if (MODE == 0) tok = p.inputs[step * BATCH + lr];

    for (int tile = start; tile < NTILES; tile += gridDim.x) {
        const int nt = tile % NT, ks = tile / NT;
        const int n0 = nt * 64, kb = ks * KC;
        float acc[4][4] = {};

        float4 ra = loadA<MODE>(p, tok, lr, kb + lk);
        float4 rb = loadB<MODE>(p, n0 + lr, kb + lk);

#pragma unroll 1
        for (int ch = 0; ch < NCH; ch++) {
            __syncthreads();
            sm.g.As[lk+0][lr] = ra.x; sm.g.As[lk+1][lr] = ra.y;
            sm.g.As[lk+2][lr] = ra.z; sm.g.As[lk+3][lr] = ra.w;
            sm.g.Bs[lk+0][lr] = rb.x; sm.g.Bs[lk+1][lr] = rb.y;
            sm.g.Bs[lk+2][lr] = rb.z; sm.g.Bs[lk+3][lr] = rb.w;
            __syncthreads();
            if (ch + 1 < NCH) {
                int k2 = kb + (ch + 1) * 16 + lk;
                ra = loadA<MODE>(p, tok, lr, k2);
                rb = loadB<MODE>(p, n0 + lr, k2);
            }
#pragma unroll
            for (int kk = 0; kk < 16; kk++) {
                float4 a4 = *reinterpret_cast<const float4*>(&sm.g.As[kk][ty * 4]);
                float4 b4 = *reinterpret_cast<const float4*>(&sm.g.Bs[kk][tx * 4]);
                acc[0][0] = fmaf(a4.x, b4.x, acc[0][0]);
                acc[0][1] = fmaf(a4.x, b4.y, acc[0][1]);
                acc[0][2] = fmaf(a4.x, b4.z, acc[0][2]);
                acc[0][3] = fmaf(a4.x, b4.w, acc[0][3]);
                acc[1][0] = fmaf(a4.y, b4.x, acc[1][0]);
                acc[1][1] = fmaf(a4.y, b4.y, acc[1][1]);
                acc[1][2] = fmaf(a4.y, b4.z, acc[1][2]);
                acc[1][3] = fmaf(a4.y, b4.w, acc[1][3]);
                acc[2][0] = fmaf(a4.z, b4.x, acc[2][0]);
                acc[2][1] = fmaf(a4.z, b4.y, acc[2][1]);
                acc[2][2] = fmaf(a4.z, b4.z, acc[2][2]);
                acc[2][3] = fmaf(a4.z, b4.w, acc[2][3]);
                acc[3][0] = fmaf(a4.w, b4.x, acc[3][0]);
                acc[3][1] = fmaf(a4.w, b4.y, acc[3][1]);
                acc[3][2] = fmaf(a4.w, b4.z, acc[3][2]);
                acc[3][3] = fmaf(a4.w, b4.w, acc[3][3]);
            }
        }

        if (MODE == 4) {
#pragma unroll
            for (int i = 0; i < 4; i++) {
#pragma unroll
                for (int j = 0; j < 4; j++) {
                    int n = n0 + tx * 4 + j;
                    if (n < VOCAB)
                        out[((size_t)(ks * BATCH + ty * 4 + i)) * LPLD + n] = acc[i][j];
                }
            }
        } else {
#pragma unroll
            for (int i = 0; i < 4; i++)
#pragma unroll
                for (int j = 0; j < 4; j++)
                    out[((size_t)(ks * BATCH + ty * 4 + i)) * NN + n0 + tx * 4 + j] = acc[i][j];
        }
    }
}

// ---------------------------------------------------------------------------
// LSTM cell (layers 0,1): combine 8 gate partials + biases. 128 blocks.
// ---------------------------------------------------------------------------
__device__ void cell_phase(const KP& p, int layer)
{
    int i = blockIdx.x * NTHR + threadIdx.x;
    if (i >= BATCH * D_DIM) return;
    const int b = i >> 9, u = i & 511;
    const float* bih = (layer == 0) ? p.b_ih0 : p.b_ih1;
    const float* bhh = (layer == 0) ? p.b_hh0 : p.b_hh1;
    float* c = (layer == 0) ? g_c1 : g_c2;
    float* h = (layer == 0) ? g_h1 : g_h2;
    float gs[4];
#pragma unroll
    for (int g = 0; g < 4; g++) {
        int idx = g * 512 + u;
        float s = bih[idx] + bhh[idx];
#pragma unroll
        for (int ss = 0; ss < 8; ss++)
            s += g_Gp[((size_t)(ss * BATCH + b)) * 2048 + idx];
        gs[g] = s;
    }
    float si = 1.f / (1.f + expf(-gs[0]));
    float sf = 1.f / (1.f + expf(-gs[1]));
    float so = 1.f / (1.f + expf(-gs[3]));
    float cc = sf * c[i] + si * tanhf(gs[2]);
    c[i] = cc;
    h[i] = so * tanhf(cc);
}

// ---------------------------------------------------------------------------
// Fused cell3 + query + attention + context. One block per batch element.
// ---------------------------------------------------------------------------
__device__ void attn_phase(const KP& p, Smem& sm, bool do_cell, float* attn_out)
{
    if (blockIdx.x >= BATCH) return;
    const int b = blockIdx.x, tid = threadIdx.x;

    if (do_cell) {
        for (int u = tid; u < D_DIM; u += NTHR) {
            float gs[4];
#pragma unroll
            for (int g = 0; g < 4; g++) {
                int idx = g * 512 + u;
                float s = p.b_ih2[idx] + p.b_hh2[idx];
#pragma unroll
                for (int ss = 0; ss < 8; ss++)
                    s += g_Gp[((size_t)(ss * BATCH + b)) * 2048 + idx];
                gs[g] = s;
            }
            float si = 1.f / (1.f + expf(-gs[0]));
            float sf = 1.f / (1.f + expf(-gs[1]));
            float so = 1.f / (1.f + expf(-gs[3]));
            float cc = sf * g_c3[b * D_DIM + u] + si * tanhf(gs[2]);
            float hh = so * tanhf(cc);
            g_c3[b * D_DIM + u] = cc;
            g_h3[b * D_DIM + u] = hh;
            sm.a.h3s[u] = hh;
        }
        __syncthreads();
        {   // q[n] = h3 . q_w[n] + q_b[n]; 2 threads per n
            int n = tid >> 1, part = tid & 1;
            const float4* wp = reinterpret_cast<const float4*>(p.q_w + (size_t)n * D_DIM + part * 256);
            const float4* hp = reinterpret_cast<const float4*>(sm.a.h3s + part * 256);
            float s = 0.f;
#pragma unroll
            for (int i = 0; i < 64; i++) {
                float4 wv = wp[i], hv = hp[i];
                s = fmaf(wv.x, hv.x, s); s = fmaf(wv.y, hv.y, s);
                s = fmaf(wv.z, hv.z, s); s = fmaf(wv.w, hv.w, s);
            }
            s += __shfl_down_sync(0xffffffffu, s, 1);
            if (part == 0) sm.a.q[n] = s + p.q_b[n];
        }
        __syncthreads();
    } else {
        for (int n = tid; n < KD; n += NTHR) sm.a.q[n] = p.q_b[n];
        __syncthreads();
    }

    const int L = p.ulen[b];
    for (int t = tid; t < TENC; t += NTHR) {
        const float4* kp = reinterpret_cast<const float4*>(p.keys + ((size_t)t * BATCH + b) * KD);
        const float4* qp = reinterpret_cast<const float4*>(sm.a.q);
        float s = 0.f;
#pragma unroll
        for (int i = 0; i < KD / 4; i++) {
            float4 kv = kp[i], qv = qp[i];
            s = fmaf(kv.x, qv.x, s); s = fmaf(kv.y, qv.y, s);
            s = fmaf(kv.z, qv.z, s); s = fmaf(kv.w, qv.w, s);
        }
        sm.a.arr[t] = (t < L) ? s : -10000.0f;
    }
    __syncthreads();

    sm.a.red[tid] = fmaxf(sm.a.arr[tid], sm.a.arr[tid + 256]);
    __syncthreads();
    for (int s = 128; s > 0; s >>= 1) {
        if (tid < s) sm.a.red[tid] = fmaxf(sm.a.red[tid], sm.a.red[tid + s]);
        __syncthreads();
    }
    const float emax = sm.a.red[0];
    __syncthreads();

    float x0 = (tid < L)       ? expf(sm.a.arr[tid]       - emax) : 0.f;
    float x1 = (tid + 256 < L) ? expf(sm.a.arr[tid + 256] - emax) : 0.f;
    sm.a.arr[tid] = x0; sm.a.arr[tid + 256] = x1;
    sm.a.red[tid] = x0 + x1;
    __syncthreads();
    for (int s = 128; s > 0; s >>= 1) {
        if (tid < s) sm.a.red[tid] += sm.a.red[tid + s];
        __syncthreads();
    }
    const float inv = 1.f / sm.a.red[0];
    __syncthreads();

    float a0 = x0 * inv, a1 = x1 * inv;
    sm.a.arr[tid] = a0; sm.a.arr[tid + 256] = a1;
    attn_out[(size_t)b * TENC + tid]       = a0;
    attn_out[(size_t)b * TENC + tid + 256] = a1;
    __syncthreads();

    {
        int v = tid & 127, c2 = tid >> 7;
        float s = 0.f;
        int tb = c2 * 256;
#pragma unroll 8
        for (int tt = tb; tt < tb + 256; tt++)
            s = fmaf(sm.a.arr[tt], p.values[((size_t)tt * BATCH + b) * VD + v], s);
        sm.a.ps[c2][v] = s;
    }
    __syncthreads();
    if (tid < VD) g_ctx[b * VD + tid] = sm.a.ps[0][tid] + sm.a.ps[1][tid];
}

// ---------------------------------------------------------------------------
// Combine p1 partials -> hid (leaky relu). 128 blocks.
// ---------------------------------------------------------------------------
__device__ void combine_hid_phase(const KP& p)
{
    int i = blockIdx.x * NTHR + threadIdx.x;
    if (i < BATCH * D_DIM) {
        int m = i >> 9, k = i & 511;
        float v = p.p1_b[k];
#pragma unroll
        for (int ss = 0; ss < 8; ss++)
            v += g_Hp[((size_t)(ss * BATCH + m)) * D_DIM + k];
        g_hid[i] = (v > 0.f) ? v : 0.01f * v;
    }
}

// ---------------------------------------------------------------------------
// Threefry-2x32 + logits combine + Gumbel argmax (blocks 0..63)
// ---------------------------------------------------------------------------
__device__ __forceinline__ void tf2x32(uint32_t k0, uint32_t k1, uint32_t x0, uint32_t x1,
                                       uint32_t& o0, uint32_t& o1)
{
    uint32_t ks2 = k0 ^ k1 ^ 0x1BD11BDAu;
    x0 += k0; x1 += k1;
#define TFR(r) { x0 += x1; x1 = (x1 << (r)) | (x1 >> (32 - (r))); x1 ^= x0; }
    TFR(13) TFR(15) TFR(26) TFR(6)   x0 += k1;  x1 += ks2 + 1u;
    TFR(17) TFR(29) TFR(16) TFR(24)  x0 += ks2; x1 += k0 + 2u;
    TFR(13) TFR(15) TFR(26) TFR(6)   x0 += k0;  x1 += k1 + 3u;
    TFR(17) TFR(29) TFR(16) TFR(24)  x0 += k1;  x1 += ks2 + 4u;
    TFR(13) TFR(15) TFR(26) TFR(6)   x0 += ks2; x1 += k0 + 5u;
#undef TFR
    o0 = x0; o1 = x1;
}

__device__ void sample_phase(const KP& p, Smem& sm, int step)
{
    if (blockIdx.x >= BATCH) return;
    const int b = blockIdx.x, tid = threadIdx.x;
    uint32_t fk0, fk1;
    tf2x32(0u, 1u, 0u, (uint32_t)step, fk0, fk1);

    float* outl = p.out_logits + ((size_t)step * BATCH + b) * VOCAB;
    float best = -__int_as_float(0x7f800000);
    int bidx = 0;
    for (int v = tid; v < VOCAB; v += NTHR) {
        float lg = p.p2_b[v];
#pragma unroll
        for (int ss = 0; ss < 8; ss++)
            lg += g_Lp[((size_t)(ss * BATCH + b)) * LPLD + v];
        outl[v] = lg;
        uint32_t o0, o1;
        tf2x32(fk0, fk1, 0u, (uint32_t)(b * VOCAB + v), o0, o1);
        uint32_t bits = o0 ^ o1;
        float u = __uint_as_float((bits >> 9) | 0x3f800000u) - 1.0f;
        float gmb = -logf(1e-10f - logf(u + 1e-10f));
        float val = lg + gmb;
        if (val > best) { best = val; bidx = v; }
    }
    sm.s.sv[tid] = best; sm.s.si[tid] = bidx;
    __syncthreads();
    for (int s = 128; s > 0; s >>= 1) {
        if (tid < s) {
            if (sm.s.sv[tid + s] > sm.s.sv[tid] ||
                (sm.s.sv[tid + s] == sm.s.sv[tid] && sm.s.si[tid + s] < sm.s.si[tid])) {
                sm.s.sv[tid] = sm.s.sv[tid + s]; sm.s.si[tid] = sm.s.si[tid + s];
            }
        }
        __syncthreads();
    }
    if (tid == 0) p.out_gen[step * BATCH + b] = (float)sm.s.si[0];
    __syncthreads();
}

// ---------------------------------------------------------------------------
// The megakernel
// ---------------------------------------------------------------------------
__global__ __launch_bounds__(NTHR, 2) void mega_kernel(KP p)
{
    __shared__ Smem sm;
    const int tid = threadIdx.x;
    unsigned e = ((volatile unsigned*)&g_relgen)[0];   // monotonic epoch base

    for (int i = blockIdx.x * NTHR + tid; i < BATCH * D_DIM; i += gridDim.x * NTHR) {
        g_h1[i] = 0.f; g_c1[i] = 0.f;
        g_h2[i] = 0.f; g_c2[i] = 0.f;
        g_h3[i] = 0.f; g_c3[i] = 0.f;
        if (i < BATCH * VD) g_ctx[i] = 0.f;
    }
    grid_sync(e);

    attn_phase(p, sm, false, g_attn_scratch);
    grid_sync(e);

    for (int t = 0; t < TDEC; t++) {
        if (t > 0) sample_phase(p, sm, t - 1);
        gemm_phase<0, 2048, 1152, 8>(p, sm, t, g_Gp);
        grid_sync(e);
        cell_phase(p, 0);
        grid_sync(e);
        gemm_phase<1, 2048, 1024, 8>(p, sm, t, g_Gp);
        grid_sync(e);
        cell_phase(p, 1);
        grid_sync(e);
        gemm_phase<2, 2048, 1024, 8>(p, sm, t, g_Gp);
        grid_sync(e);
        attn_phase(p, sm, true, p.out_attn + (size_t)t * BATCH * TENC);
        grid_sync(e);
        gemm_phase<3, 512, 640, 8>(p, sm, t, g_Hp);
        grid_sync(e);
        combine_hid_phase(p);
        grid_sync(e);
        gemm_phase<4, VOCAB, 512, 8>(p, sm, t, g_Lp);
        grid_sync(e);
    }
    sample_phase(p, sm, TDEC - 1);
}

// ---------------------------------------------------------------------------
// Host launcher — single graph node
// ---------------------------------------------------------------------------
extern "C" void kernel_launch(void* const* d_in, const int* in_sizes, int n_in,
                              void* d_out, int out_size)
{
    (void)in_sizes; (void)n_in;
    KP p;
    p.inputs = (const int*)  d_in[0];
    p.keys   = (const float*)d_in[2];
    p.values = (const float*)d_in[3];
    p.ulen   = (const int*)  d_in[4];
    p.emb    = (const float*)d_in[5];
    p.w_ih0 = (const float*)d_in[6];  p.w_hh0 = (const float*)d_in[7];
    p.b_ih0 = (const float*)d_in[8];  p.b_hh0 = (const float*)d_in[9];
    p.w_ih1 = (const float*)d_in[10]; p.w_hh1 = (const float*)d_in[11];
    p.b_ih1 = (const float*)d_in[12]; p.b_hh1 = (const float*)d_in[13];
    p.w_ih2 = (const float*)d_in[14]; p.w_hh2 = (const float*)d_in[15];
    p.b_ih2 = (const float*)d_in[16]; p.b_hh2 = (const float*)d_in[17];
    p.q_w  = (const float*)d_in[18];  p.q_b  = (const float*)d_in[19];
    p.p1_w = (const float*)d_in[20];  p.p1_b = (const float*)d_in[21];
    p.p2_b = (const float*)d_in[22];

    float* out = (float*)d_out;
    const size_t L_LOG = (size_t)TDEC * BATCH * VOCAB;
    const size_t L_ATT = (size_t)TDEC * BATCH * TENC;
    const size_t TOTAL = L_LOG + L_ATT + (size_t)TDEC * BATCH;
    const bool full = (size_t)out_size >= TOTAL;

    void* vp;
    cudaGetSymbolAddress(&vp, g_attn_scratch);
    float* pAS = (float*)vp;
    cudaGetSymbolAddress(&vp, g_gen_scratch);
    float* pGS = (float*)vp;

    p.out_logits = out;
    p.out_attn   = full ? out + L_LOG         : pAS;
    p.out_gen    = full ? out + L_LOG + L_ATT : pGS;

    int dev = 0, sms = 0;
    cudaGetDevice(&dev);
    cudaDeviceGetAttribute(&sms, cudaDevAttrMultiProcessorCount, dev);
    if (sms < 64) sms = 64;

    int occ = 1;
    cudaOccupancyMaxActiveBlocksPerMultiprocessor(&occ, mega_kernel, NTHR, 0);
    if (occ < 1) occ = 1;
    if (occ > 2) occ = 2;

    mega_kernel<<<sms * occ, NTHR>>>(p);
}

// round 6
// speedup vs baseline: 1.0830x; 1.0830x over previous
#include <cuda_runtime.h>
#include <math.h>
#include <stdint.h>
#include <stddef.h>

#define D_DIM   512
#define KD      128
#define VD      128
#define VOCAB   10001
#define BATCH   64
#define TDEC    192
#define TENC    512
#define NTHR    256
#define LPLD    10016          // padded row stride for logits partials

// ---------------------------------------------------------------------------
// Persistent state / scratch (device globals; no allocation allowed)
// ---------------------------------------------------------------------------
__device__ __align__(16) float g_h1[BATCH * D_DIM], g_c1[BATCH * D_DIM];
__device__ __align__(16) float g_h2[BATCH * D_DIM], g_c2[BATCH * D_DIM];
__device__ __align__(16) float g_h3[BATCH * D_DIM], g_c3[BATCH * D_DIM];
__device__ __align__(16) float g_ctx[BATCH * VD];
__device__ __align__(16) float g_hid[BATCH * D_DIM];
__device__ __align__(16) float g_Gp[16 * BATCH * 2048];   // LSTM gate partials (interleaved n)
__device__ __align__(16) float g_Pp[20 * BATCH * D_DIM];  // p1 partials
__device__ __align__(16) float g_Lp[4 * BATCH * LPLD];    // logits partials
__device__ __align__(16) float g_attn_scratch[BATCH * TENC];
__device__ __align__(16) float g_gen_scratch [TDEC * BATCH];
__device__ unsigned g_cntG[16];            // per-n-tile split counters (LSTM)
__device__ unsigned g_bar_count, g_bar_gen;

struct KP {
    const int*   inputs;
    const float* keys;   const float* values; const int* ulen;
    const float* emb;
    const float* w_ih0; const float* w_hh0; const float* b_ih0; const float* b_hh0;
    const float* w_ih1; const float* w_hh1; const float* b_ih1; const float* b_hh1;
    const float* w_ih2; const float* w_hh2; const float* b_ih2; const float* b_hh2;
    const float* q_w;  const float* q_b;
    const float* p1_w; const float* p1_b; const float* p2_b;
    float* out_logits; float* out_attn; float* out_gen;
};

struct __align__(16) Smem {
    union {
        struct { float As[32][64]; float Bs[32][128]; } g;    // 8KB + 16KB
        struct { float h3s[D_DIM]; float q[KD]; float arr[TENC];
                 float red[NTHR]; float ps[2][VD]; } a;
        struct { float sv[NTHR]; int si[NTHR]; } s;
    } u;
    int flag;
};

// ---------------------------------------------------------------------------
// Grid barrier (R4 atomic version — measured fastest)
// ---------------------------------------------------------------------------
__device__ __forceinline__ void grid_sync()
{
    __syncthreads();
    if (threadIdx.x == 0) {
        __threadfence();
        unsigned my = *((volatile unsigned*)&g_bar_gen);
        if (atomicAdd(&g_bar_count, 1u) == gridDim.x - 1) {
            atomicExch(&g_bar_count, 0u);
            __threadfence();
            atomicAdd(&g_bar_gen, 1u);
        } else {
            while (*((volatile unsigned*)&g_bar_gen) == my) { }
        }
        __threadfence();
    }
    __syncthreads();
}

// ---------------------------------------------------------------------------
// Virtual-operand loaders.  Mutable state via __ldcg (L2-coherent).
// ---------------------------------------------------------------------------
__device__ __forceinline__ float4 ld4(const float* p) { return *reinterpret_cast<const float4*>(p); }
__device__ __forceinline__ float4 ldcg4(const float* p) { return __ldcg(reinterpret_cast<const float4*>(p)); }

template<int MODE>
__device__ __forceinline__ float4 loadA(const KP& p, int tok, int m, int k)
{
    if (MODE == 0) {
        if (k < 512)      return ld4(p.emb + (size_t)tok * D_DIM + k);
        else if (k < 640) return ldcg4(g_ctx + m * VD + (k - 512));
        else              return ldcg4(g_h1 + m * D_DIM + (k - 640));
    } else if (MODE == 1) {
        return (k < 512) ? ldcg4(g_h1 + m * D_DIM + k) : ldcg4(g_h2 + m * D_DIM + (k - 512));
    } else if (MODE == 2) {
        return (k < 512) ? ldcg4(g_h2 + m * D_DIM + k) : ldcg4(g_h3 + m * D_DIM + (k - 512));
    } else if (MODE == 3) {
        return (k < 512) ? ldcg4(g_h3 + m * D_DIM + k) : ldcg4(g_ctx + m * VD + (k - 512));
    } else {
        return ldcg4(g_hid + m * D_DIM + k);
    }
}

// LSTM modes use gate-interleaved virtual columns: n -> phys row (n&3)*512 + (n>>2)
template<int MODE>
__device__ __forceinline__ float4 loadB(const KP& p, int n, int k)
{
    if (MODE <= 2) {
        int row = (n & 3) * 512 + (n >> 2);
        if (MODE == 0) return (k < 640) ? ld4(p.w_ih0 + (size_t)row * 640 + k)
                                        : ld4(p.w_hh0 + (size_t)row * 512 + (k - 640));
        if (MODE == 1) return (k < 512) ? ld4(p.w_ih1 + (size_t)row * 512 + k)
                                        : ld4(p.w_hh1 + (size_t)row * 512 + (k - 512));
        return (k < 512) ? ld4(p.w_ih2 + (size_t)row * 512 + k)
                         : ld4(p.w_hh2 + (size_t)row * 512 + (k - 512));
    }
    if (MODE == 3) return ld4(p.p1_w + (size_t)n * 640 + k);
    if (n < VOCAB) return ld4(p.emb + (size_t)n * D_DIM + k);
    return make_float4(0.f, 0.f, 0.f, 0.f);
}

// ---------------------------------------------------------------------------
// LSTM cell combine (runs in last-arriving split block; deterministic sum order)
// Tile nt covers units u0..u0+31 (all gates).  2048 (m,u) pairs / 256 thr = 8 each.
// ---------------------------------------------------------------------------
template<int MODE, int KSPLIT>
__device__ void lstm_combine(const KP& p, int nt)
{
    const int tid = threadIdx.x;
    const float* bih = (MODE == 0) ? p.b_ih0 : (MODE == 1) ? p.b_ih1 : p.b_ih2;
    const float* bhh = (MODE == 0) ? p.b_hh0 : (MODE == 1) ? p.b_hh1 : p.b_hh2;
    float* c = (MODE == 0) ? g_c1 : (MODE == 1) ? g_c2 : g_c3;
    float* h = (MODE == 0) ? g_h1 : (MODE == 1) ? g_h2 : g_h3;
    const int u0 = nt * 32;
#pragma unroll
    for (int j = 0; j < 8; j++) {
        int pair = tid + j * 256;
        int m = pair >> 5, u = u0 + (pair & 31);
        float4 s = make_float4(0.f, 0.f, 0.f, 0.f);
#pragma unroll
        for (int ss = 0; ss < KSPLIT; ss++) {
            float4 v = ldcg4(&g_Gp[((size_t)(ss * BATCH + m)) * 2048 + u * 4]);
            s.x += v.x; s.y += v.y; s.z += v.z; s.w += v.w;
        }
        float gi = s.x + bih[u]        + bhh[u];
        float gf = s.y + bih[512 + u]  + bhh[512 + u];
        float gg = s.z + bih[1024 + u] + bhh[1024 + u];
        float go = s.w + bih[1536 + u] + bhh[1536 + u];
        float si = 1.f / (1.f + expf(-gi));
        float sf = 1.f / (1.f + expf(-gf));
        float so = 1.f / (1.f + expf(-go));
        float cc = sf * __ldcg(&c[m * D_DIM + u]) + si * tanhf(gg);
        c[m * D_DIM + u] = cc;
        h[m * D_DIM + u] = so * tanhf(cc);
    }
}

// ---------------------------------------------------------------------------
// GEMM: 64x128 tile, 8x4 thread-tile, 32-deep chunks, reg prefetch.
// ---------------------------------------------------------------------------
template<int MODE, int NT, int KSPLIT, int KC, int NCH, bool EXCL, bool CELL>
__device__ void gemm_phase(const KP& p, Smem& sm, int step, float* out)
{
    constexpr int NTILES = NT * KSPLIT;
    const int tid = threadIdx.x;
    const int ty = tid >> 5, tx = tid & 31;
    const int arow = tid & 63;
    const int akg  = (tid >> 6) * 4;
    const int brow = tid & 127;
    const int bkg  = (tid >> 7) * 4;

    int bid = blockIdx.x, stride = gridDim.x;
    if (EXCL) { if (bid < 64) return; bid -= 64; stride -= 64; }

    int tok = 0;
    if (MODE == 0) tok = p.inputs[step * BATCH + arow];

    for (int tile = bid; tile < NTILES; tile += stride) {
        const int nt = tile % NT, ks = tile / NT;
        const int n0 = nt * 128, kb = ks * KC;
        float acc[8][4] = {};

        float4 rA0 = loadA<MODE>(p, tok, arow, kb + akg);
        float4 rA1 = loadA<MODE>(p, tok, arow, kb + akg + 16);
        float4 rB0 = loadB<MODE>(p, n0 + brow, kb + bkg);
        float4 rB1 = loadB<MODE>(p, n0 + brow, kb + bkg + 8);
        float4 rB2 = loadB<MODE>(p, n0 + brow, kb + bkg + 16);
        float4 rB3 = loadB<MODE>(p, n0 + brow, kb + bkg + 24);

#pragma unroll 1
        for (int ch = 0; ch < NCH; ch++) {
            __syncthreads();
            sm.u.g.As[akg + 0][arow] = rA0.x; sm.u.g.As[akg + 1][arow] = rA0.y;
            sm.u.g.As[akg + 2][arow] = rA0.z; sm.u.g.As[akg + 3][arow] = rA0.w;
            sm.u.g.As[akg + 16][arow] = rA1.x; sm.u.g.As[akg + 17][arow] = rA1.y;
            sm.u.g.As[akg + 18][arow] = rA1.z; sm.u.g.As[akg + 19][arow] = rA1.w;
            sm.u.g.Bs[bkg + 0][brow] = rB0.x;  sm.u.g.Bs[bkg + 1][brow] = rB0.y;
            sm.u.g.Bs[bkg + 2][brow] = rB0.z;  sm.u.g.Bs[bkg + 3][brow] = rB0.w;
            sm.u.g.Bs[bkg + 8][brow] = rB1.x;  sm.u.g.Bs[bkg + 9][brow] = rB1.y;
            sm.u.g.Bs[bkg + 10][brow] = rB1.z; sm.u.g.Bs[bkg + 11][brow] = rB1.w;
            sm.u.g.Bs[bkg + 16][brow] = rB2.x; sm.u.g.Bs[bkg + 17][brow] = rB2.y;
            sm.u.g.Bs[bkg + 18][brow] = rB2.z; sm.u.g.Bs[bkg + 19][brow] = rB2.w;
            sm.u.g.Bs[bkg + 24][brow] = rB3.x; sm.u.g.Bs[bkg + 25][brow] = rB3.y;
            sm.u.g.Bs[bkg + 26][brow] = rB3.z; sm.u.g.Bs[bkg + 27][brow] = rB3.w;
            __syncthreads();
            if (ch + 1 < NCH) {
                int k2 = kb + (ch + 1) * 32;
                rA0 = loadA<MODE>(p, tok, arow, k2 + akg);
                rA1 = loadA<MODE>(p, tok, arow, k2 + akg + 16);
                rB0 = loadB<MODE>(p, n0 + brow, k2 + bkg);
                rB1 = loadB<MODE>(p, n0 + brow, k2 + bkg + 8);
                rB2 = loadB<MODE>(p, n0 + brow, k2 + bkg + 16);
                rB3 = loadB<MODE>(p, n0 + brow, k2 + bkg + 24);
            }
#pragma unroll 8
            for (int kk = 0; kk < 32; kk++) {
                float4 a0 = *reinterpret_cast<const float4*>(&sm.u.g.As[kk][ty * 8]);
                float4 a1 = *reinterpret_cast<const float4*>(&sm.u.g.As[kk][ty * 8 + 4]);
                float4 b  = *reinterpret_cast<const float4*>(&sm.u.g.Bs[kk][tx * 4]);
                float am[8] = {a0.x, a0.y, a0.z, a0.w, a1.x, a1.y, a1.z, a1.w};
#pragma unroll
                for (int i = 0; i < 8; i++) {
                    acc[i][0] = fmaf(am[i], b.x, acc[i][0]);
                    acc[i][1] = fmaf(am[i], b.y, acc[i][1]);
                    acc[i][2] = fmaf(am[i], b.z, acc[i][2]);
                    acc[i][3] = fmaf(am[i], b.w, acc[i][3]);
                }
            }
        }

        // ---- epilogue: store partials ----
        if (MODE == 4) {
            bool edge = (n0 + 127 >= VOCAB);
#pragma unroll
            for (int i = 0; i < 8; i++) {
                size_t row = ((size_t)(ks * BATCH + ty * 8 + i)) * LPLD;
                int n = n0 + tx * 4;
                if (!edge) {
                    *reinterpret_cast<float4*>(&out[row + n]) =
                        make_float4(acc[i][0], acc[i][1], acc[i][2], acc[i][3]);
                } else {
#pragma unroll
                    for (int j = 0; j < 4; j++)
                        if (n + j < VOCAB) out[row + n + j] = acc[i][j];
                }
            }
        } else {
            const int NNout = (MODE == 3) ? 512 : 2048;
#pragma unroll
            for (int i = 0; i < 8; i++) {
                *reinterpret_cast<float4*>(
                    &out[((size_t)(ks * BATCH + ty * 8 + i)) * NNout + n0 + tx * 4]) =
                    make_float4(acc[i][0], acc[i][1], acc[i][2], acc[i][3]);
            }
        }

        if (CELL) {
            __syncthreads();                       // all stores issued
            if (tid == 0) {
                __threadfence();                   // publish partial
                sm.flag = (atomicAdd(&g_cntG[nt], 1u) == KSPLIT - 1);
            }
            __syncthreads();
            if (sm.flag) {
                __threadfence();                   // acquire others' partials
                lstm_combine<MODE, KSPLIT>(p, nt);
                if (tid == 0) g_cntG[nt] = 0;      // reset for next phase
            }
        }
    }
}

// ---------------------------------------------------------------------------
// Query + attention + context.  One block per batch element (blocks 0..63).
// ---------------------------------------------------------------------------
__device__ void attn_phase(const KP& p, Smem& sm, bool with_q, float* attn_out)
{
    if (blockIdx.x >= BATCH) return;
    const int b = blockIdx.x, tid = threadIdx.x;

    if (with_q) {
        for (int u = tid; u < D_DIM; u += NTHR)
            sm.u.a.h3s[u] = __ldcg(&g_h3[b * D_DIM + u]);
        __syncthreads();
        {   // q[n] = h3 . q_w[n] + q_b[n]; 2 threads per n
            int n = tid >> 1, part = tid & 1;
            const float4* wp = reinterpret_cast<const float4*>(p.q_w + (size_t)n * D_DIM + part * 256);
            const float4* hp = reinterpret_cast<const float4*>(sm.u.a.h3s + part * 256);
            float s = 0.f;
#pragma unroll
            for (int i = 0; i < 64; i++) {
                float4 wv = wp[i], hv = hp[i];
                s = fmaf(wv.x, hv.x, s); s = fmaf(wv.y, hv.y, s);
                s = fmaf(wv.z, hv.z, s); s = fmaf(wv.w, hv.w, s);
            }
            s += __shfl_down_sync(0xffffffffu, s, 1);
            if (part == 0) sm.u.a.q[n] = s + p.q_b[n];
        }
        __syncthreads();
    } else {
        for (int n = tid; n < KD; n += NTHR) sm.u.a.q[n] = p.q_b[n];
        __syncthreads();
    }

    const int L = p.ulen[b];
    for (int t = tid; t < TENC; t += NTHR) {
        const float4* kp = reinterpret_cast<const float4*>(p.keys + ((size_t)t * BATCH + b) * KD);
        const float4* qp = reinterpret_cast<const float4*>(sm.u.a.q);
        float s = 0.f;
#pragma unroll
        for (int i = 0; i < KD / 4; i++) {
            float4 kv = kp[i], qv = qp[i];
            s = fmaf(kv.x, qv.x, s); s = fmaf(kv.y, qv.y, s);
            s = fmaf(kv.z, qv.z, s); s = fmaf(kv.w, qv.w, s);
        }
        sm.u.a.arr[t] = (t < L) ? s : -10000.0f;
    }
    __syncthreads();

    sm.u.a.red[tid] = fmaxf(sm.u.a.arr[tid], sm.u.a.arr[tid + 256]);
    __syncthreads();
    for (int s = 128; s > 0; s >>= 1) {
        if (tid < s) sm.u.a.red[tid] = fmaxf(sm.u.a.red[tid], sm.u.a.red[tid + s]);
        __syncthreads();
    }
    const float emax = sm.u.a.red[0];
    __syncthreads();

    float x0 = (tid < L)       ? expf(sm.u.a.arr[tid]       - emax) : 0.f;
    float x1 = (tid + 256 < L) ? expf(sm.u.a.arr[tid + 256] - emax) : 0.f;
    sm.u.a.arr[tid] = x0; sm.u.a.arr[tid + 256] = x1;
    sm.u.a.red[tid] = x0 + x1;
    __syncthreads();
    for (int s = 128; s > 0; s >>= 1) {
        if (tid < s) sm.u.a.red[tid] += sm.u.a.red[tid + s];
        __syncthreads();
    }
    const float inv = 1.f / sm.u.a.red[0];
    __syncthreads();

    float a0 = x0 * inv, a1 = x1 * inv;
    sm.u.a.arr[tid] = a0; sm.u.a.arr[tid + 256] = a1;
    attn_out[(size_t)b * TENC + tid]       = a0;
    attn_out[(size_t)b * TENC + tid + 256] = a1;
    __syncthreads();

    {
        int v = tid & 127, c2 = tid >> 7;
        float s = 0.f;
        int tb = c2 * 256;
#pragma unroll 8
        for (int tt = tb; tt < tb + 256; tt++)
            s = fmaf(sm.u.a.arr[tt], p.values[((size_t)tt * BATCH + b) * VD + v], s);
        sm.u.a.ps[c2][v] = s;
    }
    __syncthreads();
    if (tid < VD) g_ctx[b * VD + tid] = sm.u.a.ps[0][tid] + sm.u.a.ps[1][tid];
}

// ---------------------------------------------------------------------------
// Combine p1 partials -> hid (leaky relu).  8192 float4s over 32 blocks.
// ---------------------------------------------------------------------------
__device__ void combine_hid_phase(const KP& p)
{
    int i = blockIdx.x * NTHR + threadIdx.x;
    if (i < BATCH * (D_DIM / 4)) {
        int m = i >> 7, kq = (i & 127) * 4;
        float4 v = ld4(p.p1_b + kq);
#pragma unroll
        for (int ss = 0; ss < 20; ss++) {
            float4 w = ldcg4(&g_Pp[((size_t)(ss * BATCH + m)) * D_DIM + kq]);
            v.x += w.x; v.y += w.y; v.z += w.z; v.w += w.w;
        }
        v.x = (v.x > 0.f) ? v.x : 0.01f * v.x;
        v.y = (v.y > 0.f) ? v.y : 0.01f * v.y;
        v.z = (v.z > 0.f) ? v.z : 0.01f * v.z;
        v.w = (v.w > 0.f) ? v.w : 0.01f * v.w;
        *reinterpret_cast<float4*>(&g_hid[m * D_DIM + kq]) = v;
    }
}

// ---------------------------------------------------------------------------
// Threefry-2x32 + logits combine + Gumbel argmax (blocks 0..63)
// ---------------------------------------------------------------------------
__device__ __forceinline__ void tf2x32(uint32_t k0, uint32_t k1, uint32_t x0, uint32_t x1,
                                       uint32_t& o0, uint32_t& o1)
{
    uint32_t ks2 = k0 ^ k1 ^ 0x1BD11BDAu;
    x0 += k0; x1 += k1;
#define TFR(r) { x0 += x1; x1 = (x1 << (r)) | (x1 >> (32 - (r))); x1 ^= x0; }
    TFR(13) TFR(15) TFR(26) TFR(6)   x0 += k1;  x1 += ks2 + 1u;
    TFR(17) TFR(29) TFR(16) TFR(24)  x0 += ks2; x1 += k0 + 2u;
    TFR(13) TFR(15) TFR(26) TFR(6)   x0 += k0;  x1 += k1 + 3u;
    TFR(17) TFR(29) TFR(16) TFR(24)  x0 += k1;  x1 += ks2 + 4u;
    TFR(13) TFR(15) TFR(26) TFR(6)   x0 += ks2; x1 += k0 + 5u;
#undef TFR
    o0 = x0; o1 = x1;
}

__device__ void sample_phase(const KP& p, Smem& sm, int step)
{
    if (blockIdx.x >= BATCH) return;
    const int b = blockIdx.x, tid = threadIdx.x;
    uint32_t fk0, fk1;
    tf2x32(0u, 1u, 0u, (uint32_t)step, fk0, fk1);

    float* outl = p.out_logits + ((size_t)step * BATCH + b) * VOCAB;
    float best = -__int_as_float(0x7f800000);
    int bidx = 0;
    for (int v = tid; v < VOCAB; v += NTHR) {
        float lg = p.p2_b[v];
#pragma unroll
        for (int ss = 0; ss < 4; ss++)
            lg += __ldcg(&g_Lp[((size_t)(ss * BATCH + b)) * LPLD + v]);
        outl[v] = lg;
        uint32_t o0, o1;
        tf2x32(fk0, fk1, 0u, (uint32_t)(b * VOCAB + v), o0, o1);
        uint32_t bits = o0 ^ o1;
        float u = __uint_as_float((bits >> 9) | 0x3f800000u) - 1.0f;
        float gmb = -logf(1e-10f - logf(u + 1e-10f));
        float val = lg + gmb;
        if (val > best) { best = val; bidx = v; }
    }
    sm.u.s.sv[tid] = best; sm.u.s.si[tid] = bidx;
    __syncthreads();
    for (int s = 128; s > 0; s >>= 1) {
        if (tid < s) {
            if (sm.u.s.sv[tid + s] > sm.u.s.sv[tid] ||
                (sm.u.s.sv[tid + s] == sm.u.s.sv[tid] && sm.u.s.si[tid + s] < sm.u.s.si[tid])) {
                sm.u.s.sv[tid] = sm.u.s.sv[tid + s]; sm.u.s.si[tid] = sm.u.s.si[tid + s];
            }
        }
        __syncthreads();
    }
    if (tid == 0) p.out_gen[step * BATCH + b] = (float)sm.u.s.si[0];
    __syncthreads();
}

// ---------------------------------------------------------------------------
// The megakernel — 7 barriers/step
// ---------------------------------------------------------------------------
__global__ __launch_bounds__(NTHR, 2) void mega_kernel(KP p)
{
    __shared__ Smem sm;
    const int tid = threadIdx.x;

    for (int i = blockIdx.x * NTHR + tid; i < BATCH * D_DIM; i += gridDim.x * NTHR) {
        g_h1[i] = 0.f; g_c1[i] = 0.f;
        g_h2[i] = 0.f; g_c2[i] = 0.f;
        g_h3[i] = 0.f; g_c3[i] = 0.f;
        if (i < BATCH * VD) g_ctx[i] = 0.f;
    }
    grid_sync();

    attn_phase(p, sm, false, g_attn_scratch);
    grid_sync();

    for (int t = 0; t < TDEC; t++) {
        if (t > 0) sample_phase(p, sm, t - 1);
        gemm_phase<0, 16, 12,  96, 3, true,  true >(p, sm, t, g_Gp);   // lstm0 + cell
        grid_sync();
        gemm_phase<1, 16, 16,  64, 2, false, true >(p, sm, t, g_Gp);   // lstm1 + cell
        grid_sync();
        gemm_phase<2, 16, 16,  64, 2, false, true >(p, sm, t, g_Gp);   // lstm2 + cell
        grid_sync();
        attn_phase(p, sm, true, p.out_attn + (size_t)t * BATCH * TENC);
        grid_sync();
        gemm_phase<3,  4, 20,  32, 1, false, false>(p, sm, t, g_Pp);   // p1
        grid_sync();
        combine_hid_phase(p);
        grid_sync();
        gemm_phase<4, 79,  4, 128, 4, false, false>(p, sm, t, g_Lp);   // logits
        grid_sync();
    }
    sample_phase(p, sm, TDEC - 1);
}

// ---------------------------------------------------------------------------
// Host launcher — single graph node
// ---------------------------------------------------------------------------
extern "C" void kernel_launch(void* const* d_in, const int* in_sizes, int n_in,
                              void* d_out, int out_size)
{
    (void)in_sizes; (void)n_in;
    KP p;
    p.inputs = (const int*)  d_in[0];
    p.keys   = (const float*)d_in[2];
    p.values = (const float*)d_in[3];
    p.ulen   = (const int*)  d_in[4];
    p.emb    = (const float*)d_in[5];
    p.w_ih0 = (const float*)d_in[6];  p.w_hh0 = (const float*)d_in[7];
    p.b_ih0 = (const float*)d_in[8];  p.b_hh0 = (const float*)d_in[9];
    p.w_ih1 = (const float*)d_in[10]; p.w_hh1 = (const float*)d_in[11];
    p.b_ih1 = (const float*)d_in[12]; p.b_hh1 = (const float*)d_in[13];
    p.w_ih2 = (const float*)d_in[14]; p.w_hh2 = (const float*)d_in[15];
    p.b_ih2 = (const float*)d_in[16]; p.b_hh2 = (const float*)d_in[17];
    p.q_w  = (const float*)d_in[18];  p.q_b  = (const float*)d_in[19];
    p.p1_w = (const float*)d_in[20];  p.p1_b = (const float*)d_in[21];
    p.p2_b = (const float*)d_in[22];

    float* out = (float*)d_out;
    const size_t L_LOG = (size_t)TDEC * BATCH * VOCAB;
    const size_t L_ATT = (size_t)TDEC * BATCH * TENC;
    const size_t TOTAL = L_LOG + L_ATT + (size_t)TDEC * BATCH;
    const bool full = (size_t)out_size >= TOTAL;

    void* vp;
    cudaGetSymbolAddress(&vp, g_attn_scratch);
    float* pAS = (float*)vp;
    cudaGetSymbolAddress(&vp, g_gen_scratch);
    float* pGS = (float*)vp;

    p.out_logits = out;
    p.out_attn   = full ? out + L_LOG         : pAS;
    p.out_gen    = full ? out + L_LOG + L_ATT : pGS;

    int dev = 0, sms = 0;
    cudaGetDevice(&dev);
    cudaDeviceGetAttribute(&sms, cudaDevAttrMultiProcessorCount, dev);
    if (sms < 64) sms = 64;

    int occ = 1;
    cudaOccupancyMaxActiveBlocksPerMultiprocessor(&occ, mega_kernel, NTHR, 0);
    if (occ < 1) occ = 1;
    if (occ > 2) occ = 2;

    mega_kernel<<<sms * occ, NTHR>>>(p);
}

// round 7
// speedup vs baseline: 1.1258x; 1.0395x over previous
#include <cuda_runtime.h>
#include <math.h>
#include <stdint.h>
#include <stddef.h>

#define D_DIM   512
#define KD      128
#define VD      128
#define VOCAB   10001
#define BATCH   64
#define TDEC    192
#define TENC    512
#define NTHR    512
#define LPLD    10016          // padded row stride for logits partials

// ---------------------------------------------------------------------------
// Persistent state / scratch (device globals; no allocation allowed)
// ---------------------------------------------------------------------------
__device__ __align__(16) float g_h1[BATCH * D_DIM], g_c1[BATCH * D_DIM];
__device__ __align__(16) float g_h2[BATCH * D_DIM], g_c2[BATCH * D_DIM];
__device__ __align__(16) float g_h3[BATCH * D_DIM], g_c3[BATCH * D_DIM];
__device__ __align__(16) float g_ctx[BATCH * VD];
__device__ __align__(16) float g_hid[BATCH * D_DIM];
__device__ __align__(16) float g_Gp[16 * BATCH * 2048];   // LSTM gate partials (interleaved n)
__device__ __align__(16) float g_Pp[20 * BATCH * D_DIM];  // p1 partials
__device__ __align__(16) float g_Lp[8 * BATCH * LPLD];    // logits partials
__device__ __align__(16) float g_attn_scratch[BATCH * TENC];
__device__ __align__(16) float g_gen_scratch [TDEC * BATCH];
__device__ unsigned g_cntG[16];            // per-n-tile split counters (LSTM)
__device__ unsigned g_bar_count, g_bar_gen;

struct KP {
    const int*   inputs;
    const float* keys;   const float* values; const int* ulen;
    const float* emb;
    const float* w_ih0; const float* w_hh0; const float* b_ih0; const float* b_hh0;
    const float* w_ih1; const float* w_hh1; const float* b_ih1; const float* b_hh1;
    const float* w_ih2; const float* w_hh2; const float* b_ih2; const float* b_hh2;
    const float* q_w;  const float* q_b;
    const float* p1_w; const float* p1_b; const float* p2_b;
    float* out_logits; float* out_attn; float* out_gen;
};

struct __align__(16) Smem {
    union {
        struct { float As[32][64]; float Bs[32][128]; } g;    // 8KB + 16KB
        struct { float h3s[D_DIM]; float q[KD]; float arr[TENC];
                 float red[NTHR]; float ps[4][VD]; } a;
        struct { float sv[NTHR]; int si[NTHR]; } s;
    } u;
    int flag;
};

// ---------------------------------------------------------------------------
// Grid barrier (R4 atomic version — measured fastest; grid unchanged at 304)
// ---------------------------------------------------------------------------
__device__ __forceinline__ void grid_sync()
{
    __syncthreads();
    if (threadIdx.x == 0) {
        __threadfence();
        unsigned my = *((volatile unsigned*)&g_bar_gen);
        if (atomicAdd(&g_bar_count, 1u) == gridDim.x - 1) {
            atomicExch(&g_bar_count, 0u);
            __threadfence();
            atomicAdd(&g_bar_gen, 1u);
        } else {
            while (*((volatile unsigned*)&g_bar_gen) == my) { }
        }
        __threadfence();
    }
    __syncthreads();
}

// ---------------------------------------------------------------------------
// Virtual-operand loaders.  Mutable state via __ldcg (L2-coherent).
// ---------------------------------------------------------------------------
__device__ __forceinline__ float4 ld4(const float* p) { return *reinterpret_cast<const float4*>(p); }
__device__ __forceinline__ float4 ldcg4(const float* p) { return __ldcg(reinterpret_cast<const float4*>(p)); }

template<int MODE>
__device__ __forceinline__ float4 loadA(const KP& p, int tok, int m, int k)
{
    if (MODE == 0) {
        if (k < 512)      return ld4(p.emb + (size_t)tok * D_DIM + k);
        else if (k < 640) return ldcg4(g_ctx + m * VD + (k - 512));
        else              return ldcg4(g_h1 + m * D_DIM + (k - 640));
    } else if (MODE == 1) {
        return (k < 512) ? ldcg4(g_h1 + m * D_DIM + k) : ldcg4(g_h2 + m * D_DIM + (k - 512));
    } else if (MODE == 2) {
        return (k < 512) ? ldcg4(g_h2 + m * D_DIM + k) : ldcg4(g_h3 + m * D_DIM + (k - 512));
    } else if (MODE == 3) {
        return (k < 512) ? ldcg4(g_h3 + m * D_DIM + k) : ldcg4(g_ctx + m * VD + (k - 512));
    } else {
        return ldcg4(g_hid + m * D_DIM + k);
    }
}

// LSTM modes use gate-interleaved virtual columns: n -> phys row (n&3)*512 + (n>>2)
template<int MODE>
__device__ __forceinline__ float4 loadB(const KP& p, int n, int k)
{
    if (MODE <= 2) {
        int row = (n & 3) * 512 + (n >> 2);
        if (MODE == 0) return (k < 640) ? ld4(p.w_ih0 + (size_t)row * 640 + k)
                                        : ld4(p.w_hh0 + (size_t)row * 512 + (k - 640));
        if (MODE == 1) return (k < 512) ? ld4(p.w_ih1 + (size_t)row * 512 + k)
                                        : ld4(p.w_hh1 + (size_t)row * 512 + (k - 512));
        return (k < 512) ? ld4(p.w_ih2 + (size_t)row * 512 + k)
                         : ld4(p.w_hh2 + (size_t)row * 512 + (k - 512));
    }
    if (MODE == 3) return ld4(p.p1_w + (size_t)n * 640 + k);
    if (n < VOCAB) return ld4(p.emb + (size_t)n * D_DIM + k);
    return make_float4(0.f, 0.f, 0.f, 0.f);
}

// ---------------------------------------------------------------------------
// LSTM cell combine (runs in last-arriving split block; deterministic order)
// Tile nt covers units u0..u0+31 (all gates). 2048 (m,u) pairs / 512 thr = 4.
// ---------------------------------------------------------------------------
template<int MODE, int KSPLIT>
__device__ void lstm_combine(const KP& p, int nt)
{
    const int tid = threadIdx.x;
    const float* bih = (MODE == 0) ? p.b_ih0 : (MODE == 1) ? p.b_ih1 : p.b_ih2;
    const float* bhh = (MODE == 0) ? p.b_hh0 : (MODE == 1) ? p.b_hh1 : p.b_hh2;
    float* c = (MODE == 0) ? g_c1 : (MODE == 1) ? g_c2 : g_c3;
    float* h = (MODE == 0) ? g_h1 : (MODE == 1) ? g_h2 : g_h3;
    const int u0 = nt * 32;
#pragma unroll
    for (int j = 0; j < 4; j++) {
        int pair = tid + j * NTHR;
        int m = pair >> 5, u = u0 + (pair & 31);
        float4 s = make_float4(0.f, 0.f, 0.f, 0.f);
#pragma unroll
        for (int ss = 0; ss < KSPLIT; ss++) {
            float4 v = ldcg4(&g_Gp[((size_t)(ss * BATCH + m)) * 2048 + u * 4]);
            s.x += v.x; s.y += v.y; s.z += v.z; s.w += v.w;
        }
        float gi = s.x + bih[u]        + bhh[u];
        float gf = s.y + bih[512 + u]  + bhh[512 + u];
        float gg = s.z + bih[1024 + u] + bhh[1024 + u];
        float go = s.w + bih[1536 + u] + bhh[1536 + u];
        float si = 1.f / (1.f + expf(-gi));
        float sf = 1.f / (1.f + expf(-gf));
        float so = 1.f / (1.f + expf(-go));
        float cc = sf * __ldcg(&c[m * D_DIM + u]) + si * tanhf(gg);
        c[m * D_DIM + u] = cc;
        h[m * D_DIM + u] = so * tanhf(cc);
    }
}

// ---------------------------------------------------------------------------
// GEMM: 64x128 tile, 512 threads, 4x4 thread-tile, 32-deep chunks, prefetch.
// ---------------------------------------------------------------------------
template<int MODE, int NT, int KSPLIT, int KC, int NCH, bool EXCL, bool CELL>
__device__ void gemm_phase(const KP& p, Smem& sm, int step, float* out)
{
    constexpr int NTILES = NT * KSPLIT;
    const int tid = threadIdx.x;
    const int ty = tid >> 5, tx = tid & 31;      // 16 x 32 compute grid
    const int arow = tid & 63;
    const int akg  = (tid >> 6) * 4;             // 0..28
    const int brow = tid & 127;
    const int bkg  = (tid >> 7) * 4;             // 0,4,8,12

    int bid = blockIdx.x, stride = gridDim.x;
    if (EXCL) { if (bid < 64) return; bid -= 64; stride -= 64; }

    int tok = 0;
    if (MODE == 0) tok = p.inputs[step * BATCH + arow];

    for (int tile = bid; tile < NTILES; tile += stride) {
        const int nt = tile % NT, ks = tile / NT;
        const int n0 = nt * 128, kb = ks * KC;
        float acc[4][4] = {};

        float4 rA  = loadA<MODE>(p, tok, arow, kb + akg);
        float4 rB0 = loadB<MODE>(p, n0 + brow, kb + bkg);
        float4 rB1 = loadB<MODE>(p, n0 + brow, kb + bkg + 16);

#pragma unroll 1
        for (int ch = 0; ch < NCH; ch++) {
            __syncthreads();
            sm.u.g.As[akg + 0][arow] = rA.x;  sm.u.g.As[akg + 1][arow] = rA.y;
            sm.u.g.As[akg + 2][arow] = rA.z;  sm.u.g.As[akg + 3][arow] = rA.w;
            sm.u.g.Bs[bkg + 0][brow] = rB0.x; sm.u.g.Bs[bkg + 1][brow] = rB0.y;
            sm.u.g.Bs[bkg + 2][brow] = rB0.z; sm.u.g.Bs[bkg + 3][brow] = rB0.w;
            sm.u.g.Bs[bkg + 16][brow] = rB1.x; sm.u.g.Bs[bkg + 17][brow] = rB1.y;
            sm.u.g.Bs[bkg + 18][brow] = rB1.z; sm.u.g.Bs[bkg + 19][brow] = rB1.w;
            __syncthreads();
            if (ch + 1 < NCH) {
                int k2 = kb + (ch + 1) * 32;
                rA  = loadA<MODE>(p, tok, arow, k2 + akg);
                rB0 = loadB<MODE>(p, n0 + brow, k2 + bkg);
                rB1 = loadB<MODE>(p, n0 + brow, k2 + bkg + 16);
            }
#pragma unroll 8
            for (int kk = 0; kk < 32; kk++) {
                float4 a4 = *reinterpret_cast<const float4*>(&sm.u.g.As[kk][ty * 4]);
                float4 b4 = *reinterpret_cast<const float4*>(&sm.u.g.Bs[kk][tx * 4]);
                acc[0][0] = fmaf(a4.x, b4.x, acc[0][0]);
                acc[0][1] = fmaf(a4.x, b4.y, acc[0][1]);
                acc[0][2] = fmaf(a4.x, b4.z, acc[0][2]);
                acc[0][3] = fmaf(a4.x, b4.w, acc[0][3]);
                acc[1][0] = fmaf(a4.y, b4.x, acc[1][0]);
                acc[1][1] = fmaf(a4.y, b4.y, acc[1][1]);
                acc[1][2] = fmaf(a4.y, b4.z, acc[1][2]);
                acc[1][3] = fmaf(a4.y, b4.w, acc[1][3]);
                acc[2][0] = fmaf(a4.z, b4.x, acc[2][0]);
                acc[2][1] = fmaf(a4.z, b4.y, acc[2][1]);
                acc[2][2] = fmaf(a4.z, b4.z, acc[2][2]);
                acc[2][3] = fmaf(a4.z, b4.w, acc[2][3]);
                acc[3][0] = fmaf(a4.w, b4.x, acc[3][0]);
                acc[3][1] = fmaf(a4.w, b4.y, acc[3][1]);
                acc[3][2] = fmaf(a4.w, b4.z, acc[3][2]);
                acc[3][3] = fmaf(a4.w, b4.w, acc[3][3]);
            }
        }

        // ---- epilogue: store partials ----
        if (MODE == 4) {
            bool edge = (n0 + 127 >= VOCAB);
#pragma unroll
            for (int i = 0; i < 4; i++) {
                size_t row = ((size_t)(ks * BATCH + ty * 4 + i)) * LPLD;
                int n = n0 + tx * 4;
                if (!edge) {
                    *reinterpret_cast<float4*>(&out[row + n]) =
                        make_float4(acc[i][0], acc[i][1], acc[i][2], acc[i][3]);
                } else {
#pragma unroll
                    for (int j = 0; j < 4; j++)
                        if (n + j < VOCAB) out[row + n + j] = acc[i][j];
                }
            }
        } else {
            const int NNout = (MODE == 3) ? 512 : 2048;
#pragma unroll
            for (int i = 0; i < 4; i++) {
                *reinterpret_cast<float4*>(
                    &out[((size_t)(ks * BATCH + ty * 4 + i)) * NNout + n0 + tx * 4]) =
                    make_float4(acc[i][0], acc[i][1], acc[i][2], acc[i][3]);
            }
        }

        if (CELL) {
            __syncthreads();                       // all stores issued
            if (tid == 0) {
                __threadfence();                   // publish partial
                sm.flag = (atomicAdd(&g_cntG[nt], 1u) == KSPLIT - 1);
            }
            __syncthreads();
            if (sm.flag) {
                __threadfence();                   // acquire others' partials
                lstm_combine<MODE, KSPLIT>(p, nt);
                if (tid == 0) g_cntG[nt] = 0;      // reset for next phase
            }
        }
    }
}

// ---------------------------------------------------------------------------
// Query + attention + context.  One block per batch element (blocks 0..63).
// 512 threads: one encoder position each.
// ---------------------------------------------------------------------------
__device__ void attn_phase(const KP& p, Smem& sm, bool with_q, float* attn_out)
{
    if (blockIdx.x >= BATCH) return;
    const int b = blockIdx.x, tid = threadIdx.x;

    if (with_q) {
        sm.u.a.h3s[tid] = __ldcg(&g_h3[b * D_DIM + tid]);
        __syncthreads();
        {   // q[n] = h3 . q_w[n] + q_b[n]; 4 threads per n (quad shuffle reduce)
            int n = tid >> 2, part = tid & 3;
            const float4* wp = reinterpret_cast<const float4*>(p.q_w + (size_t)n * D_DIM + part * 128);
            const float4* hp = reinterpret_cast<const float4*>(sm.u.a.h3s + part * 128);
            float s = 0.f;
#pragma unroll
            for (int i = 0; i < 32; i++) {
                float4 wv = wp[i], hv = hp[i];
                s = fmaf(wv.x, hv.x, s); s = fmaf(wv.y, hv.y, s);
                s = fmaf(wv.z, hv.z, s); s = fmaf(wv.w, hv.w, s);
            }
            s += __shfl_down_sync(0xffffffffu, s, 1);
            s += __shfl_down_sync(0xffffffffu, s, 2);
            if (part == 0) sm.u.a.q[n] = s + p.q_b[n];
        }
        __syncthreads();
    } else {
        if (tid < KD) sm.u.a.q[tid] = p.q_b[tid];
        __syncthreads();
    }

    const int L = p.ulen[b];
    float e;
    {
        const float4* kp = reinterpret_cast<const float4*>(p.keys + ((size_t)tid * BATCH + b) * KD);
        const float4* qp = reinterpret_cast<const float4*>(sm.u.a.q);
        float s = 0.f;
#pragma unroll
        for (int i = 0; i < KD / 4; i++) {
            float4 kv = kp[i], qv = qp[i];
            s = fmaf(kv.x, qv.x, s); s = fmaf(kv.y, qv.y, s);
            s = fmaf(kv.z, qv.z, s); s = fmaf(kv.w, qv.w, s);
        }
        e = (tid < L) ? s : -10000.0f;
    }
    sm.u.a.red[tid] = e;
    __syncthreads();
    for (int s = 256; s > 0; s >>= 1) {
        if (tid < s) sm.u.a.red[tid] = fmaxf(sm.u.a.red[tid], sm.u.a.red[tid + s]);
        __syncthreads();
    }
    const float emax = sm.u.a.red[0];
    __syncthreads();

    float x = (tid < L) ? expf(e - emax) : 0.f;
    sm.u.a.red[tid] = x;
    __syncthreads();
    for (int s = 256; s > 0; s >>= 1) {
        if (tid < s) sm.u.a.red[tid] += sm.u.a.red[tid + s];
        __syncthreads();
    }
    const float inv = 1.f / sm.u.a.red[0];
    __syncthreads();

    float a = x * inv;
    sm.u.a.arr[tid] = a;
    attn_out[(size_t)b * TENC + tid] = a;
    __syncthreads();

    {   // ctx[v] = sum_t a[t] * values[t][b][v]; 4 t-chunks of 128
        int v = tid & 127, c4 = tid >> 7;
        float s = 0.f;
        int tb = c4 * 128;
#pragma unroll 8
        for (int tt = tb; tt < tb + 128; tt++)
            s = fmaf(sm.u.a.arr[tt], p.values[((size_t)tt * BATCH + b) * VD + v], s);
        sm.u.a.ps[c4][v] = s;
    }
    __syncthreads();
    if (tid < VD)
        g_ctx[b * VD + tid] = sm.u.a.ps[0][tid] + sm.u.a.ps[1][tid]
                            + sm.u.a.ps[2][tid] + sm.u.a.ps[3][tid];
}

// ---------------------------------------------------------------------------
// Combine p1 partials -> hid (leaky relu). 8192 float4s over 16 blocks.
// ---------------------------------------------------------------------------
__device__ void combine_hid_phase(const KP& p)
{
    int i = blockIdx.x * NTHR + threadIdx.x;
    if (i < BATCH * (D_DIM / 4)) {
        int m = i >> 7, kq = (i & 127) * 4;
        float4 v = ld4(p.p1_b + kq);
#pragma unroll
        for (int ss = 0; ss < 20; ss++) {
            float4 w = ldcg4(&g_Pp[((size_t)(ss * BATCH + m)) * D_DIM + kq]);
            v.x += w.x; v.y += w.y; v.z += w.z; v.w += w.w;
        }
        v.x = (v.x > 0.f) ? v.x : 0.01f * v.x;
        v.y = (v.y > 0.f) ? v.y : 0.01f * v.y;
        v.z = (v.z > 0.f) ? v.z : 0.01f * v.z;
        v.w = (v.w > 0.f) ? v.w : 0.01f * v.w;
        *reinterpret_cast<float4*>(&g_hid[m * D_DIM + kq]) = v;
    }
}

// ---------------------------------------------------------------------------
// Threefry-2x32 + logits combine + Gumbel argmax (blocks 0..63)
// ---------------------------------------------------------------------------
__device__ __forceinline__ void tf2x32(uint32_t k0, uint32_t k1, uint32_t x0, uint32_t x1,
                                       uint32_t& o0, uint32_t& o1)
{
    uint32_t ks2 = k0 ^ k1 ^ 0x1BD11BDAu;
    x0 += k0; x1 += k1;
#define TFR(r) { x0 += x1; x1 = (x1 << (r)) | (x1 >> (32 - (r))); x1 ^= x0; }
    TFR(13) TFR(15) TFR(26) TFR(6)   x0 += k1;  x1 += ks2 + 1u;
    TFR(17) TFR(29) TFR(16) TFR(24)  x0 += ks2; x1 += k0 + 2u;
    TFR(13) TFR(15) TFR(26) TFR(6)   x0 += k0;  x1 += k1 + 3u;
    TFR(17) TFR(29) TFR(16) TFR(24)  x0 += k1;  x1 += ks2 + 4u;
    TFR(13) TFR(15) TFR(26) TFR(6)   x0 += ks2; x1 += k0 + 5u;
#undef TFR
    o0 = x0; o1 = x1;
}

__device__ void sample_phase(const KP& p, Smem& sm, int step)
{
    if (blockIdx.x >= BATCH) return;
    const int b = blockIdx.x, tid = threadIdx.x;
    uint32_t fk0, fk1;
    tf2x32(0u, 1u, 0u, (uint32_t)step, fk0, fk1);

    float* outl = p.out_logits + ((size_t)step * BATCH + b) * VOCAB;
    float best = -__int_as_float(0x7f800000);
    int bidx = 0;
    for (int v = tid; v < VOCAB; v += NTHR) {
        float lg = p.p2_b[v];
#pragma unroll
        for (int ss = 0; ss < 8; ss++)
            lg += __ldcg(&g_Lp[((size_t)(ss * BATCH + b)) * LPLD + v]);
        outl[v] = lg;
        uint32_t o0, o1;
        tf2x32(fk0, fk1, 0u, (uint32_t)(b * VOCAB + v), o0, o1);
        uint32_t bits = o0 ^ o1;
        float u = __uint_as_float((bits >> 9) | 0x3f800000u) - 1.0f;
        float gmb = -logf(1e-10f - logf(u + 1e-10f));
        float val = lg + gmb;
        if (val > best) { best = val; bidx = v; }
    }
    sm.u.s.sv[tid] = best; sm.u.s.si[tid] = bidx;
    __syncthreads();
    for (int s = 256; s > 0; s >>= 1) {
        if (tid < s) {
            if (sm.u.s.sv[tid + s] > sm.u.s.sv[tid] ||
                (sm.u.s.sv[tid + s] == sm.u.s.sv[tid] && sm.u.s.si[tid + s] < sm.u.s.si[tid])) {
                sm.u.s.sv[tid] = sm.u.s.sv[tid + s]; sm.u.s.si[tid] = sm.u.s.si[tid + s];
            }
        }
        __syncthreads();
    }
    if (tid == 0) p.out_gen[step * BATCH + b] = (float)sm.u.s.si[0];
    __syncthreads();
}

// ---------------------------------------------------------------------------
// The megakernel — 7 barriers/step, 32 warps/SM
// ---------------------------------------------------------------------------
__global__ __launch_bounds__(NTHR, 2) void mega_kernel(KP p)
{
    __shared__ Smem sm;
    const int tid = threadIdx.x;

    for (int i = blockIdx.x * NTHR + tid; i < BATCH * D_DIM; i += gridDim.x * NTHR) {
        g_h1[i] = 0.f; g_c1[i] = 0.f;
        g_h2[i] = 0.f; g_c2[i] = 0.f;
        g_h3[i] = 0.f; g_c3[i] = 0.f;
        if (i < BATCH * VD) g_ctx[i] = 0.f;
    }
    grid_sync();

    attn_phase(p, sm, false, g_attn_scratch);
    grid_sync();

    for (int t = 0; t < TDEC; t++) {
        if (t > 0) sample_phase(p, sm, t - 1);
        gemm_phase<0, 16, 12,  96, 3, true,  true >(p, sm, t, g_Gp);   // lstm0 + cell
        grid_sync();
        gemm_phase<1, 16, 16,  64, 2, false, true >(p, sm, t, g_Gp);   // lstm1 + cell
        grid_sync();
        gemm_phase<2, 16, 16,  64, 2, false, true >(p, sm, t, g_Gp);   // lstm2 + cell
        grid_sync();
        attn_phase(p, sm, true, p.out_attn + (size_t)t * BATCH * TENC);
        grid_sync();
        gemm_phase<3,  4, 20,  32, 1, false, false>(p, sm, t, g_Pp);   // p1
        grid_sync();
        combine_hid_phase(p);
        grid_sync();
        gemm_phase<4, 79,  8,  64, 2, false, false>(p, sm, t, g_Lp);   // logits
        grid_sync();
    }
    sample_phase(p, sm, TDEC - 1);
}

// ---------------------------------------------------------------------------
// Host launcher — single graph node
// ---------------------------------------------------------------------------
extern "C" void kernel_launch(void* const* d_in, const int* in_sizes, int n_in,
                              void* d_out, int out_size)
{
    (void)in_sizes; (void)n_in;
    KP p;
    p.inputs = (const int*)  d_in[0];
    p.keys   = (const float*)d_in[2];
    p.values = (const float*)d_in[3];
    p.ulen   = (const int*)  d_in[4];
    p.emb    = (const float*)d_in[5];
    p.w_ih0 = (const float*)d_in[6];  p.w_hh0 = (const float*)d_in[7];
    p.b_ih0 = (const float*)d_in[8];  p.b_hh0 = (const float*)d_in[9];
    p.w_ih1 = (const float*)d_in[10]; p.w_hh1 = (const float*)d_in[11];
    p.b_ih1 = (const float*)d_in[12]; p.b_hh1 = (const float*)d_in[13];
    p.w_ih2 = (const float*)d_in[14]; p.w_hh2 = (const float*)d_in[15];
    p.b_ih2 = (const float*)d_in[16]; p.b_hh2 = (const float*)d_in[17];
    p.q_w  = (const float*)d_in[18];  p.q_b  = (const float*)d_in[19];
    p.p1_w = (const float*)d_in[20];  p.p1_b = (const float*)d_in[21];
    p.p2_b = (const float*)d_in[22];

    float* out = (float*)d_out;
    const size_t L_LOG = (size_t)TDEC * BATCH * VOCAB;
    const size_t L_ATT = (size_t)TDEC * BATCH * TENC;
    const size_t TOTAL = L_LOG + L_ATT + (size_t)TDEC * BATCH;
    const bool full = (size_t)out_size >= TOTAL;

    void* vp;
    cudaGetSymbolAddress(&vp, g_attn_scratch);
    float* pAS = (float*)vp;
    cudaGetSymbolAddress(&vp, g_gen_scratch);
    float* pGS = (float*)vp;

    p.out_logits = out;
    p.out_attn   = full ? out + L_LOG         : pAS;
    p.out_gen    = full ? out + L_LOG + L_ATT : pGS;

    int dev = 0, sms = 0;
    cudaGetDevice(&dev);
    cudaDeviceGetAttribute(&sms, cudaDevAttrMultiProcessorCount, dev);
    if (sms < 64) sms = 64;

    int occ = 1;
    cudaOccupancyMaxActiveBlocksPerMultiprocessor(&occ, mega_kernel, NTHR, 0);
    if (occ < 1) occ = 1;
    if (occ > 2) occ = 2;

    mega_kernel<<<sms * occ, NTHR>>>(p);
}